// round 10
// baseline (speedup 1.0000x reference)
#include <cuda_runtime.h>
#include <cstdint>

// ----------------------------------------------------------------------------
// B=128, T=32, F=2048, H=1024, L=20, WV=300; TF gate order i,j,f,o; FORGET_BIAS=1
// ----------------------------------------------------------------------------
#define B_   128
#define T_   32
#define F_   2048
#define H_   1024
#define L_   20
#define WV_  300
#define G4H  4096
#define NBLK 128
#define STG_WORDS 6144       // mm0_big stage: A 128x16 (2048) + B 16x256 (4096)
#define SMEM_BIG  (3 * STG_WORDS * 4)

// persist: resident B 256x128 fp32 + 3-stage A pipeline 128x16 fp32
#define KSP     256
#define BRES_F  32768                      // 256*128
#define APIPE_F (3 * 2048)
#define SMEM_PST ((BRES_F + APIPE_F) * 4)  // 155648 bytes

// ---------------- device scratch ----------------
__device__ float g_xg_enc[(size_t)4096 * 4096];   // [t*128+b][4H]
__device__ float g_xg_dec[(size_t)2560 * 4096];   // [l*128+b][4H]
__device__ float g_zp[(size_t)128 * 128 * 128];   // [bid][batch 128][local n 128]
__device__ float g_hbuf[2][B_ * H_];              // double-buffered h (tf32-rounded)
__device__ float g_hs[(size_t)L_ * B_ * H_];      // decoder outputs
__device__ float g_whE[(size_t)H_ * G4H];         // tf32-rounded Wh (encoder)
__device__ float g_whD[(size_t)H_ * G4H];         // tf32-rounded Wh (decoder)
__device__ float g_wx[(size_t)F_ * G4H];          // tf32-rounded Wx (encoder, [k][n])
__device__ float g_frames_tf[(size_t)4096 * F_];  // [m=t*128+b][k] tf32 frames
__device__ unsigned g_flagZ[NBLK * 8];
__device__ unsigned g_flagH[NBLK * 8];

// ---------------- helpers ----------------
__device__ __forceinline__ float f2tf(float x) {
    unsigned u;
    asm("cvt.rna.tf32.f32 %0, %1;" : "=r"(u) : "f"(x));
    return __uint_as_float(u);
}
__device__ __forceinline__ float4 tf4(float4 v) {
    return make_float4(f2tf(v.x), f2tf(v.y), f2tf(v.z), f2tf(v.w));
}
__device__ __forceinline__ void mma8(float* c, const float* a, const float* b) {
    asm volatile(
        "mma.sync.aligned.m16n8k8.row.col.f32.tf32.tf32.f32 "
        "{%0,%1,%2,%3},{%4,%5,%6,%7},{%8,%9},{%0,%1,%2,%3};"
        : "+f"(c[0]), "+f"(c[1]), "+f"(c[2]), "+f"(c[3])
        : "r"(__float_as_uint(a[0])), "r"(__float_as_uint(a[1])),
          "r"(__float_as_uint(a[2])), "r"(__float_as_uint(a[3])),
          "r"(__float_as_uint(b[0])), "r"(__float_as_uint(b[1])));
}
__device__ __forceinline__ float sigf(float x) { return 1.f / (1.f + __expf(-x)); }

__device__ __forceinline__ uint32_t smem_u32(const void* p) {
    return (uint32_t)__cvta_generic_to_shared(p);
}
__device__ __forceinline__ void cpa16(uint32_t dst, const void* src) {
    asm volatile("cp.async.cg.shared.global [%0], [%1], 16;" :: "r"(dst), "l"(src));
}
#define CP_COMMIT() asm volatile("cp.async.commit_group;")
#define CP_WAIT1()  asm volatile("cp.async.wait_group 1;")

// ============================================================================
// mm0_big (R8, passing): enc XG GEMM, tile 128x256, BK=16, cp.async 3-stage.
// ============================================================================
struct CoreIds {
    int lane, wid, wm, wn, gid, tig, swzA;
    int ar, akq, a_dst;
    int bk, bn, b_dst;
};
__device__ __forceinline__ CoreIds core_ids(int tid) {
    CoreIds s;
    s.lane = tid & 31; s.wid = tid >> 5;
    s.wm = s.wid >> 2; s.wn = s.wid & 3;
    s.gid = s.lane >> 2; s.tig = s.lane & 3;
    s.swzA = ((s.gid >> 1) & 3) << 2;
    s.ar = tid >> 2; s.akq = (tid & 3) << 2;
    s.a_dst = s.ar * 16 + (s.akq ^ (((s.ar >> 1) & 3) << 2));
    s.bk = tid >> 5; s.bn = (tid & 31) * 8;
    s.b_dst = 2048 + s.bk * 256 + (s.bn ^ ((s.bk & 3) << 3));
    return s;
}

__device__ __forceinline__ void core_compute(
    const float* __restrict__ a_s, const float* __restrict__ b_s,
    const CoreIds& s, float acc[2][8][4])
{
#pragma unroll
    for (int ks = 0; ks < 16; ks += 8) {
        float af[2][4], bf[8][2];
#pragma unroll
        for (int mf = 0; mf < 2; mf++) {
            const int m0 = s.wm * 32 + mf * 16 + s.gid;
            const int c0 = (ks + s.tig) ^ s.swzA;
            const int c1 = (ks + s.tig + 4) ^ s.swzA;
            af[mf][0] = a_s[m0 * 16 + c0];
            af[mf][1] = a_s[(m0 + 8) * 16 + c0];
            af[mf][2] = a_s[m0 * 16 + c1];
            af[mf][3] = a_s[(m0 + 8) * 16 + c1];
        }
#pragma unroll
        for (int nf = 0; nf < 8; nf++) {
            const int n = (s.wn * 64 + nf * 8 + s.gid) ^ (s.tig << 3);
            bf[nf][0] = b_s[(ks + s.tig) * 256 + n];
            bf[nf][1] = b_s[(ks + s.tig + 4) * 256 + n];
        }
#pragma unroll
        for (int mf = 0; mf < 2; mf++)
#pragma unroll
            for (int nf = 0; nf < 8; nf++) mma8(acc[mf][nf], af[mf], bf[nf]);
    }
}

__global__ void __launch_bounds__(512)
mm0_big(const float* __restrict__ bias)
{
    extern __shared__ float dsm[];
    const int tid = threadIdx.x;
    const CoreIds s = core_ids(tid);
    const uint32_t smb = smem_u32(dsm);
    const int ntile = blockIdx.x, mtile = blockIdx.y;

    const float* arow = g_frames_tf + (size_t)(mtile * 128 + s.ar) * F_;
    const float* bsrc = g_wx + ntile * 256 + s.bn;

    float acc[2][8][4] = {};
    const int NK = F_ / 16;

    auto issue = [&](int st) {
        const uint32_t sb = smb + (uint32_t)((st % 3) * STG_WORDS) * 4;
        const int kb = st * 16;
        cpa16(sb + s.a_dst * 4, arow + kb + s.akq);
        const float* bp = bsrc + (size_t)(kb + s.bk) * G4H;
        cpa16(sb + s.b_dst * 4, bp);
        cpa16(sb + (s.b_dst + 4) * 4, bp + 4);
    };

    issue(0); CP_COMMIT();
    issue(1); CP_COMMIT();

    for (int kt = 0; kt < NK; ++kt) {
        CP_WAIT1();
        __syncthreads();
        if (kt + 2 < NK) issue(kt + 2);
        CP_COMMIT();
        const float* a_s = dsm + (kt % 3) * STG_WORDS;
        core_compute(a_s, a_s + 2048, s, acc);
    }

#pragma unroll
    for (int mf = 0; mf < 2; mf++)
#pragma unroll
        for (int nf = 0; nf < 8; nf++) {
            const int col = ntile * 256 + s.wn * 64 + nf * 8 + 2 * s.tig;
            const float2 bb = *(const float2*)(bias + col);
#pragma unroll
            for (int r = 0; r < 2; r++) {
                const int row = mtile * 128 + s.wm * 32 + mf * 16 + s.gid + r * 8;
                *(float2*)&g_xg_enc[(size_t)row * G4H + col] =
                    make_float2(acc[mf][nf][2 * r] + bb.x,
                                acc[mf][nf][2 * r + 1] + bb.y);
            }
        }
}

// ============================================================================
// Persistent recurrence with RESIDENT B: 32 n-groups x 4 k-splits.
// Block (g = bid>>2, ks = bid&3):
//   b_res (smem, loaded once per phase) = Wh[k0..k0+256][cols {gt*1024+g*32..+32}]
//   per step: z partials via tf32 mma (A = h via cp.async pipeline),
//   group sync (4 blocks) -> gates for b in [ks*32..+32) x hc in [g*32..+32),
//   c in registers -> full barrier.
// ============================================================================
__global__ void __launch_bounds__(512)
lstm_persist()
{
    extern __shared__ float dsm[];
    float* b_res = dsm;                 // [256][128] fp32, XOR-swizzled
    float* a_pipe = dsm + BRES_F;       // 3 x (128x16)

    const int tid = threadIdx.x, bid = blockIdx.x;
    const int g = bid >> 2, ks = bid & 3;
    const int k0 = ks * KSP;

    const int lane = tid & 31, wid = tid >> 5;
    const int wm = wid >> 2, wn = wid & 3;
    const int gid = lane >> 2, tig = lane & 3;
    const int swzA = ((gid >> 1) & 3) << 2;

    const int ar = tid >> 2, akq = (tid & 3) << 2;
    const int a_dst = ar * 16 + (akq ^ (((ar >> 1) & 3) << 2));
    const uint32_t smA = smem_u32(a_pipe);

    // resident-B loader ids: thread loads 16 float4 (rows bkr+16i, col granule bn4)
    const int bkr = tid >> 5;           // 0..15
    const int bn4 = (tid & 31) * 4;     // 0..124 (local n granule)
    const size_t bcol = (size_t)(bn4 >> 5) * 1024 + g * 32 + (bn4 & 31);

    // gate ids: thread owns (gb, ghc), (gb, ghc+1)
    const int rb = tid >> 4, rc = (tid & 15) * 2;
    const int gb = ks * 32 + rb;
    const int ghc = g * 32 + rc;
    float2 creg = make_float2(0.f, 0.f);

    for (int t = 0; t < T_ + L_; ++t) {
        const bool dec = (t >= T_);
        const int st = dec ? t - T_ : t;
        const float* hsrc = g_hbuf[t & 1];
        const float* xg = (dec ? g_xg_dec : g_xg_enc) + (size_t)st * (B_ * G4H);

        // load resident B once per phase (Wh already tf32-rounded)
        if (t == 0 || t == T_) {
            const float* wh = dec ? g_whD : g_whE;
#pragma unroll
            for (int i = 0; i < 16; i++) {
                const int k = i * 16 + bkr;
                const float4 v = *(const float4*)(wh + (size_t)(k0 + k) * G4H + bcol);
                *(float4*)&b_res[k * 128 + (bn4 ^ ((k & 3) << 3))] = v;
            }
            __syncthreads();
        }

        float acc[2][4][4] = {};

        auto issueA = [&](int si) {
            const uint32_t sb = smA + (uint32_t)((si % 3) * 2048) * 4;
            cpa16(sb + a_dst * 4, hsrc + (size_t)ar * H_ + k0 + si * 16 + akq);
        };
        issueA(0); CP_COMMIT();
        issueA(1); CP_COMMIT();

        for (int kt = 0; kt < 16; ++kt) {
            CP_WAIT1();
            __syncthreads();
            if (kt + 2 < 16) issueA(kt + 2);
            CP_COMMIT();

            const float* a_s = a_pipe + (kt % 3) * 2048;
            const int kl0 = kt * 16;
#pragma unroll
            for (int kss = 0; kss < 16; kss += 8) {
                float af[2][4], bf[4][2];
#pragma unroll
                for (int mf = 0; mf < 2; mf++) {
                    const int m0 = wm * 32 + mf * 16 + gid;
                    const int c0 = (kss + tig) ^ swzA;
                    const int c1 = (kss + tig + 4) ^ swzA;
                    af[mf][0] = a_s[m0 * 16 + c0];
                    af[mf][1] = a_s[(m0 + 8) * 16 + c0];
                    af[mf][2] = a_s[m0 * 16 + c1];
                    af[mf][3] = a_s[(m0 + 8) * 16 + c1];
                }
#pragma unroll
                for (int nf = 0; nf < 4; nf++) {
                    const int nn = wn * 32 + nf * 8 + gid;
                    const int r0 = kl0 + kss + tig;         // (r0 & 3) == tig
                    bf[nf][0] = b_res[r0 * 128 + (nn ^ (tig << 3))];
                    bf[nf][1] = b_res[(r0 + 4) * 128 + (nn ^ (tig << 3))];
                }
#pragma unroll
                for (int mf = 0; mf < 2; mf++)
#pragma unroll
                    for (int nf = 0; nf < 4; nf++) mma8(acc[mf][nf], af[mf], bf[nf]);
            }
        }

        // ---- store z partials: g_zp[bid][row][local n 0..127] ----
#pragma unroll
        for (int mf = 0; mf < 2; mf++)
#pragma unroll
            for (int nf = 0; nf < 4; nf++) {
                const int col = wn * 32 + nf * 8 + 2 * tig;
#pragma unroll
                for (int r = 0; r < 2; r++) {
                    const int row = wm * 32 + mf * 16 + gid + r * 8;
                    *(float2*)&g_zp[((size_t)bid * 128 + row) * 128 + col] =
                        make_float2(acc[mf][nf][2 * r], acc[mf][nf][2 * r + 1]);
                }
            }

        // ---- group sync (4 k-split blocks of this n-group) ----
        __syncthreads();
        __threadfence();
        if (tid == 0) *(volatile unsigned*)&g_flagZ[bid * 8] = (unsigned)(t + 1);
        if (tid < 4) {
            volatile unsigned* f = &g_flagZ[(g * 4 + tid) * 8];
            while (*f < (unsigned)(t + 1)) {}
        }
        __threadfence();
        __syncthreads();

        // ---- gates: b in [ks*32..+32) x hc in [g*32..+32) ----
        {
            float2 z[4];
#pragma unroll
            for (int gt = 0; gt < 4; gt++) {
                float2 v = *(const float2*)(xg + (size_t)gb * G4H + gt * 1024 + ghc);
#pragma unroll
                for (int kp = 0; kp < 4; kp++) {
                    const float2 p = __ldcg((const float2*)(
                        &g_zp[((size_t)(g * 4 + kp) * 128 + gb) * 128 + gt * 32 + rc]));
                    v.x += p.x; v.y += p.y;
                }
                z[gt] = v;
            }
            float2 hn;
            {
                const float ig = sigf(z[0].x);
                const float jg = tanhf(z[1].x);
                const float fg = sigf(z[2].x + 1.0f);   // FORGET_BIAS
                const float og = sigf(z[3].x);
                creg.x = creg.x * fg + ig * jg;
                hn.x = tanhf(creg.x) * og;
            }
            {
                const float ig = sigf(z[0].y);
                const float jg = tanhf(z[1].y);
                const float fg = sigf(z[2].y + 1.0f);
                const float og = sigf(z[3].y);
                creg.y = creg.y * fg + ig * jg;
                hn.y = tanhf(creg.y) * og;
            }
            const float2 ho = make_float2(f2tf(hn.x), f2tf(hn.y));
            *(float2*)(g_hbuf[(t + 1) & 1] + (size_t)gb * H_ + ghc) = ho;
            if (dec)
                *(float2*)(g_hs + ((size_t)st * B_ + gb) * H_ + ghc) = ho;
        }

        // ---- full barrier ----
        __syncthreads();
        __threadfence();
        if (tid == 0) *(volatile unsigned*)&g_flagH[bid * 8] = (unsigned)(t + 1);
        if (tid < NBLK) {
            volatile unsigned* f = &g_flagH[tid * 8];
            while (*f < (unsigned)(t + 1)) __nanosleep(64);
        }
        __threadfence();
        __syncthreads();
    }
}

// ============================================================================
// mm_tf32 (R8, passing): MODE 1 (dec XG, gather), MODE 2 (projection)
// ============================================================================
#define ASTR 20
#define BSTR 136
struct TIds {
    int lane, wid, wm, wn, gid, tig;
    int ar, ak, bk, bn;
};
__device__ __forceinline__ TIds make_ids(int tid) {
    TIds s;
    s.lane = tid & 31; s.wid = tid >> 5;
    s.wm = s.wid >> 2; s.wn = s.wid & 3;
    s.gid = s.lane >> 2; s.tig = s.lane & 3;
    s.ar = tid >> 2; s.ak = (tid & 3) * 4;
    s.bk = tid >> 5; s.bn = (tid & 31) * 4;
    return s;
}
__device__ __forceinline__ void compute_bk16(
    const float* a_s, const float* b_s, const TIds& s, float acc[2][4][4])
{
#pragma unroll
    for (int ks = 0; ks < 16; ks += 8) {
        float af[2][4], bf[4][2];
#pragma unroll
        for (int mf = 0; mf < 2; mf++) {
            const int m = s.wm * 32 + mf * 16 + s.gid;
            af[mf][0] = a_s[(m)     * ASTR + ks + s.tig];
            af[mf][1] = a_s[(m + 8) * ASTR + ks + s.tig];
            af[mf][2] = a_s[(m)     * ASTR + ks + s.tig + 4];
            af[mf][3] = a_s[(m + 8) * ASTR + ks + s.tig + 4];
        }
#pragma unroll
        for (int nf = 0; nf < 4; nf++) {
            const int n = s.wn * 32 + nf * 8 + s.gid;
            bf[nf][0] = b_s[(ks + s.tig)     * BSTR + n];
            bf[nf][1] = b_s[(ks + s.tig + 4) * BSTR + n];
        }
#pragma unroll
        for (int mf = 0; mf < 2; mf++)
#pragma unroll
            for (int nf = 0; nf < 4; nf++) mma8(acc[mf][nf], af[mf], bf[nf]);
    }
}

template <int MODE>
__global__ void __launch_bounds__(512)
mm_tf32(const float* __restrict__ A, const float* __restrict__ Bm,
        const float* __restrict__ bias, float* __restrict__ Cout,
        const int* __restrict__ caption, int Kv, int ldb)
{
    __shared__ __align__(16) float a_s[2][128 * ASTR];
    __shared__ __align__(16) float b_s[2][16 * BSTR];

    const int tid = threadIdx.x;
    const TIds s = make_ids(tid);
    const int n0 = blockIdx.x * 128;
    const int mtile = blockIdx.y;

    const int m = mtile * 128 + s.ar;
    size_t aoff;
    if constexpr (MODE == 1)
        aoff = (size_t)caption[(m & 127) * L_ + (m >> 7)] * WV_;
    else
        aoff = (size_t)m * H_;
    const float* arow = ((MODE == 2) ? (const float*)g_hs : A) + aoff;

    float acc[2][4][4] = {};
    const int NK = (Kv + 15) / 16;

    auto stage = [&](int it, int buf) {
        const int kb = it * 16;
        {
            const int gk = kb + s.ak;
            float4 v = make_float4(0.f, 0.f, 0.f, 0.f);
            if (MODE != 1 || gk < Kv) v = *(const float4*)(arow + gk);
            *(float4*)&a_s[buf][s.ar * ASTR + s.ak] = tf4(v);
        }
        {
            const int gk = kb + s.bk;
            const int gn = n0 + s.bn;
            float4 v = make_float4(0.f, 0.f, 0.f, 0.f);
            const bool kok = (MODE == 1) ? (gk < Kv) : true;
            const bool nok = (MODE == 2) ? (gn < WV_) : true;
            if (kok && nok) v = *(const float4*)(Bm + (size_t)gk * ldb + gn);
            *(float4*)&b_s[buf][s.bk * BSTR + s.bn] = tf4(v);
        }
    };

    stage(0, 0);
    __syncthreads();
    int buf = 0;
    for (int it = 0; it < NK; ++it) {
        if (it + 1 < NK) stage(it + 1, buf ^ 1);
        compute_bk16(a_s[buf], b_s[buf], s, acc);
        __syncthreads();
        buf ^= 1;
    }

#pragma unroll
    for (int mf = 0; mf < 2; mf++)
#pragma unroll
        for (int nf = 0; nf < 4; nf++) {
            const int col = n0 + s.wn * 32 + nf * 8 + 2 * s.tig;
            const int mrow = mtile * 128 + s.wm * 32 + mf * 16 + s.gid;
#pragma unroll
            for (int r = 0; r < 2; r++) {
                const int row = mrow + r * 8;
                const float v0 = acc[mf][nf][2 * r];
                const float v1 = acc[mf][nf][2 * r + 1];
                if constexpr (MODE == 2) {
                    if (col < WV_) {
                        const size_t co = (size_t)((row & 127) * L_ + (row >> 7)) * WV_;
                        Cout[co + col]     = v0 + bias[col];
                        Cout[co + col + 1] = v1 + bias[col + 1];
                    }
                } else {
                    float* dst = g_xg_dec + (size_t)row * G4H + col;
                    *(float2*)dst = make_float2(v0 + bias[col], v1 + bias[col + 1]);
                }
            }
        }
}

// ---- prep kernels (R8, passing) ----
__global__ void __launch_bounds__(512)
conv_wh(const float* __restrict__ encK, const float* __restrict__ decK)
{
    const size_t i4 = ((size_t)blockIdx.x * 512 + threadIdx.x) * 4;
    if (i4 < (size_t)H_ * G4H) {
        *(float4*)&g_whE[i4] = tf4(*(const float4*)(encK + (size_t)F_  * G4H + i4));
        *(float4*)&g_whD[i4] = tf4(*(const float4*)(decK + (size_t)WV_ * G4H + i4));
    }
}

__global__ void __launch_bounds__(512)
conv_wx(const float* __restrict__ encK)
{
    const size_t i4 = ((size_t)blockIdx.x * 512 + threadIdx.x) * 4;
    if (i4 < (size_t)F_ * G4H)
        *(float4*)&g_wx[i4] = tf4(*(const float4*)(encK + i4));
}

__global__ void __launch_bounds__(512)
prep_frames(const float* __restrict__ frames)
{
    const size_t i4 = ((size_t)blockIdx.x * 512 + threadIdx.x) * 4;
    if (i4 < (size_t)4096 * F_) {
        const int m = (int)(i4 / F_), k = (int)(i4 % F_);
        const int b = m & 127, t = m >> 7;
        const float4 v = *(const float4*)(frames + ((size_t)b * T_ + t) * F_ + k);
        *(float4*)&g_frames_tf[i4] = tf4(v);
    }
}

__global__ void init_k()
{
    const int i = blockIdx.x * 256 + threadIdx.x;
    if (i < B_ * H_) g_hbuf[0][i] = 0.f;
    if (i < NBLK * 8) { g_flagZ[i] = 0u; g_flagH[i] = 0u; }
}

// ----------------------------------------------------------------------------
extern "C" void kernel_launch(void* const* d_in, const int* in_sizes, int n_in,
                              void* d_out, int out_size)
{
    const float* frames  = (const float*)d_in[0];
    const int*   caption = (const int*)  d_in[1];
    const float* emb     = (const float*)d_in[2];
    const float* encK    = (const float*)d_in[3];
    const float* encB    = (const float*)d_in[4];
    const float* decK    = (const float*)d_in[5];
    const float* decB    = (const float*)d_in[6];
    const float* projW   = (const float*)d_in[7];
    const float* projB   = (const float*)d_in[8];
    float*       out     = (float*)d_out;

    cudaFuncSetAttribute(mm0_big, cudaFuncAttributeMaxDynamicSharedMemorySize, SMEM_BIG);
    cudaFuncSetAttribute(lstm_persist, cudaFuncAttributeMaxDynamicSharedMemorySize, SMEM_PST);

    init_k<<<512, 256>>>();
    conv_wh<<<2048, 512>>>(encK, decK);
    conv_wx<<<4096, 512>>>(encK);
    prep_frames<<<4096, 512>>>(frames);

    // encoder input gates: [4096,2048] x [2048,4096] + enc_bias
    mm0_big<<<dim3(16, 32), 512, SMEM_BIG>>>(encB);

    // decoder input gates: gather(emb) [2560,300] x [300,4096] + dec_bias
    mm_tf32<1><<<dim3(32, 20), 512>>>(emb, decK, decB, nullptr, caption, WV_, G4H);

    // full recurrence (32 enc + 20 dec), resident-B persistent kernel
    lstm_persist<<<NBLK, 512, SMEM_PST>>>();

    // projection: [2560,1024] x [1024,300] + proj_b -> out[b][l][wv]
    mm_tf32<2><<<dim3(3, 20), 512>>>(nullptr, projW, projB, out, nullptr, H_, WV_);
}

// round 11
// speedup vs baseline: 1.5270x; 1.5270x over previous
#include <cuda_runtime.h>
#include <cstdint>

// ----------------------------------------------------------------------------
// B=128, T=32, F=2048, H=1024, L=20, WV=300; TF gate order i,j,f,o; FORGET_BIAS=1
// ----------------------------------------------------------------------------
#define B_   128
#define T_   32
#define F_   2048
#define H_   1024
#define L_   20
#define WV_  300
#define G4H  4096
#define NBLK 128
#define NSTG 3
#define STG_WORDS 6144       // mm0_big stage: A 128x16 (2048) + B 16x256 (4096)
#define SMEM_BIG  (3 * STG_WORDS * 4)

// ---------------- device scratch ----------------
__device__ float g_xg_enc[(size_t)4096 * 4096];   // [t*128+b][4H]
__device__ float g_xg_dec[(size_t)2560 * 4096];   // [l*128+b][4H]
__device__ float g_zp[(size_t)128 * 128 * 128];   // [bid][batch 128][gatecol 128]
__device__ float g_hbuf[2][B_ * H_];              // double-buffered h (tf32-rounded)
__device__ float g_hs[(size_t)L_ * B_ * H_];      // decoder outputs
__device__ float g_whE[(size_t)H_ * G4H];         // tf32-rounded Wh (encoder)
__device__ float g_whD[(size_t)H_ * G4H];         // tf32-rounded Wh (decoder)
__device__ float g_wx[(size_t)F_ * G4H];          // tf32-rounded Wx (encoder, [k][n])
__device__ float g_frames_tf[(size_t)4096 * F_];  // [m=t*128+b][k] tf32 frames
__device__ unsigned g_flagZ[NBLK * 8];
__device__ unsigned g_flagH[NBLK * 8];

// ---------------- helpers ----------------
__device__ __forceinline__ float f2tf(float x) {
    unsigned u;
    asm("cvt.rna.tf32.f32 %0, %1;" : "=r"(u) : "f"(x));
    return __uint_as_float(u);
}
__device__ __forceinline__ float4 tf4(float4 v) {
    return make_float4(f2tf(v.x), f2tf(v.y), f2tf(v.z), f2tf(v.w));
}
__device__ __forceinline__ void mma8(float* c, const float* a, const float* b) {
    asm volatile(
        "mma.sync.aligned.m16n8k8.row.col.f32.tf32.tf32.f32 "
        "{%0,%1,%2,%3},{%4,%5,%6,%7},{%8,%9},{%0,%1,%2,%3};"
        : "+f"(c[0]), "+f"(c[1]), "+f"(c[2]), "+f"(c[3])
        : "r"(__float_as_uint(a[0])), "r"(__float_as_uint(a[1])),
          "r"(__float_as_uint(a[2])), "r"(__float_as_uint(a[3])),
          "r"(__float_as_uint(b[0])), "r"(__float_as_uint(b[1])));
}
__device__ __forceinline__ float2 add2(float2 a, float2 b) {
    a.x += b.x; a.y += b.y; return a;
}
__device__ __forceinline__ float sigf(float x) { return 1.f / (1.f + __expf(-x)); }

__device__ __forceinline__ uint32_t smem_u32(const void* p) {
    return (uint32_t)__cvta_generic_to_shared(p);
}
__device__ __forceinline__ void cpa16(uint32_t dst, const void* src) {
    asm volatile("cp.async.cg.shared.global [%0], [%1], 16;" :: "r"(dst), "l"(src));
}
#define CP_COMMIT() asm volatile("cp.async.commit_group;")
#define CP_WAIT1()  asm volatile("cp.async.wait_group 1;")

// ============================================================================
// mm0_big (R8, measured 132 TF/s): enc XG GEMM, tile 128x256, BK=16, 3-stage.
// ============================================================================
struct CoreIds {
    int lane, wid, wm, wn, gid, tig, swzA;
    int ar, akq, a_dst;
    int bk, bn, b_dst;
};
__device__ __forceinline__ CoreIds core_ids(int tid) {
    CoreIds s;
    s.lane = tid & 31; s.wid = tid >> 5;
    s.wm = s.wid >> 2; s.wn = s.wid & 3;
    s.gid = s.lane >> 2; s.tig = s.lane & 3;
    s.swzA = ((s.gid >> 1) & 3) << 2;
    s.ar = tid >> 2; s.akq = (tid & 3) << 2;
    s.a_dst = s.ar * 16 + (s.akq ^ (((s.ar >> 1) & 3) << 2));
    s.bk = tid >> 5; s.bn = (tid & 31) * 8;
    s.b_dst = 2048 + s.bk * 256 + (s.bn ^ ((s.bk & 3) << 3));
    return s;
}

__device__ __forceinline__ void core_compute(
    const float* __restrict__ a_s, const float* __restrict__ b_s,
    const CoreIds& s, float acc[2][8][4])
{
#pragma unroll
    for (int ks = 0; ks < 16; ks += 8) {
        float af[2][4], bf[8][2];
#pragma unroll
        for (int mf = 0; mf < 2; mf++) {
            const int m0 = s.wm * 32 + mf * 16 + s.gid;
            const int c0 = (ks + s.tig) ^ s.swzA;
            const int c1 = (ks + s.tig + 4) ^ s.swzA;
            af[mf][0] = a_s[m0 * 16 + c0];
            af[mf][1] = a_s[(m0 + 8) * 16 + c0];
            af[mf][2] = a_s[m0 * 16 + c1];
            af[mf][3] = a_s[(m0 + 8) * 16 + c1];
        }
#pragma unroll
        for (int nf = 0; nf < 8; nf++) {
            const int n = (s.wn * 64 + nf * 8 + s.gid) ^ (s.tig << 3);
            bf[nf][0] = b_s[(ks + s.tig) * 256 + n];
            bf[nf][1] = b_s[(ks + s.tig + 4) * 256 + n];
        }
#pragma unroll
        for (int mf = 0; mf < 2; mf++)
#pragma unroll
            for (int nf = 0; nf < 8; nf++) mma8(acc[mf][nf], af[mf], bf[nf]);
    }
}

__global__ void __launch_bounds__(512)
mm0_big(const float* __restrict__ bias)
{
    extern __shared__ float dsm[];
    const int tid = threadIdx.x;
    const CoreIds s = core_ids(tid);
    const uint32_t smb = smem_u32(dsm);
    const int ntile = blockIdx.x, mtile = blockIdx.y;

    const float* arow = g_frames_tf + (size_t)(mtile * 128 + s.ar) * F_;
    const float* bsrc = g_wx + ntile * 256 + s.bn;

    float acc[2][8][4] = {};
    const int NK = F_ / 16;

    auto issue = [&](int st) {
        const uint32_t sb = smb + (uint32_t)((st % 3) * STG_WORDS) * 4;
        const int kb = st * 16;
        cpa16(sb + s.a_dst * 4, arow + kb + s.akq);
        const float* bp = bsrc + (size_t)(kb + s.bk) * G4H;
        cpa16(sb + s.b_dst * 4, bp);
        cpa16(sb + (s.b_dst + 4) * 4, bp + 4);
    };

    issue(0); CP_COMMIT();
    issue(1); CP_COMMIT();

    for (int kt = 0; kt < NK; ++kt) {
        CP_WAIT1();
        __syncthreads();
        if (kt + 2 < NK) issue(kt + 2);
        CP_COMMIT();
        const float* a_s = dsm + (kt % 3) * STG_WORDS;
        core_compute(a_s, a_s + 2048, s, acc);
    }

#pragma unroll
    for (int mf = 0; mf < 2; mf++)
#pragma unroll
        for (int nf = 0; nf < 8; nf++) {
            const int col = ntile * 256 + s.wn * 64 + nf * 8 + 2 * s.tig;
            const float2 bb = *(const float2*)(bias + col);
#pragma unroll
            for (int r = 0; r < 2; r++) {
                const int row = mtile * 128 + s.wm * 32 + mf * 16 + s.gid + r * 8;
                *(float2*)&g_xg_enc[(size_t)row * G4H + col] =
                    make_float2(acc[mf][nf][2 * r] + bb.x,
                                acc[mf][nf][2 * r + 1] + bb.y);
            }
        }
}

// ============================================================================
// Persistent recurrence (R6, measured ~10.8us/step): 32 n-groups x 4 k-splits,
// cp.async 3-stage (A and B streamed), 32x32 warp tile.
// Only change vs R6: xg gate inputs preloaded at step start (latency hidden
// under the GEMM phase). Numerics identical.
// ============================================================================
__global__ void __launch_bounds__(512)
lstm_persist()
{
    __shared__ __align__(16) float sm[NSTG][4096];   // per stage: A[2048] | B[2048]

    const int tid = threadIdx.x, bid = blockIdx.x;
    const int gid_n = bid >> 2, ks = bid & 3;
    const int hc0 = gid_n * 32;
    const int k0 = ks * 256;

    const int lane = tid & 31, wid = tid >> 5;
    const int wm = wid >> 2, wn = wid & 3;
    const int gid = lane >> 2, tig = lane & 3;
    const int swzA = ((gid >> 1) & 3) << 2;
    const int swzB = tig * 8;

    const int ar = tid >> 2, akq = (tid & 3) * 4;
    const int a_dst = ar * 16 + (akq ^ (((ar >> 1) & 3) << 2));
    const int bk = tid >> 5, bseg = (tid & 31) >> 3, bnn = (tid & 7) * 4;
    const int b_dst = 2048 + bk * 128 + ((bseg * 32 + bnn) ^ ((bk & 3) * 8));
    const size_t b_srcoff = (size_t)bk * G4H + bseg * 1024 + hc0 + bnn;

    const uint32_t smb = (uint32_t)__cvta_generic_to_shared(&sm[0][0]);

    // gate ids: thread owns 2 elements (gb, ghc), (gb, ghc+1)
    const int li = tid * 2, rb = li >> 5, rc = li & 31;
    const int gb = ks * 32 + rb;
    const int ghc = hc0 + rc;
    float2 creg = make_float2(0.f, 0.f);

    for (int t = 0; t < T_ + L_; ++t) {
        const bool dec = (t >= T_);
        const int st = dec ? t - T_ : t;
        const float* wh = dec ? g_whD : g_whE;
        const float* hsrc = g_hbuf[t & 1];
        const float* xg = (dec ? g_xg_dec : g_xg_enc) + (size_t)st * (B_ * G4H);

        // preload xg gate inputs for this thread (consumed after group sync;
        // latency hidden under the GEMM below). Same values as before.
        float2 zx[4];
#pragma unroll
        for (int g = 0; g < 4; g++)
            zx[g] = *(const float2*)(xg + (size_t)gb * G4H + g * 1024 + ghc);

        float acc[2][4][4] = {};

        auto issue = [&](int sidx) {
            const int kb = k0 + sidx * 16;
            const uint32_t sb = smb + (uint32_t)((sidx % NSTG) * 4096 * 4);
            cpa16(sb + a_dst * 4, hsrc + (size_t)ar * H_ + kb + akq);
            cpa16(sb + b_dst * 4, wh + (size_t)kb * G4H + b_srcoff);
        };

        issue(0); CP_COMMIT();
        issue(1); CP_COMMIT();

        for (int kt = 0; kt < 16; ++kt) {
            CP_WAIT1();
            __syncthreads();
            if (kt + 2 < 16) issue(kt + 2);
            CP_COMMIT();

            const float* a_s = &sm[0][0] + (kt % NSTG) * 4096;
            const float* b_s = a_s + 2048;
#pragma unroll
            for (int kss = 0; kss < 16; kss += 8) {
                float af[2][4], bf[4][2];
#pragma unroll
                for (int mf = 0; mf < 2; mf++) {
                    const int m0 = wm * 32 + mf * 16 + gid;
                    const int c0 = (kss + tig) ^ swzA;
                    const int c1 = (kss + tig + 4) ^ swzA;
                    af[mf][0] = a_s[m0 * 16 + c0];
                    af[mf][1] = a_s[(m0 + 8) * 16 + c0];
                    af[mf][2] = a_s[m0 * 16 + c1];
                    af[mf][3] = a_s[(m0 + 8) * 16 + c1];
                }
#pragma unroll
                for (int nf = 0; nf < 4; nf++) {
                    const int n = wn * 32 + nf * 8 + gid;
                    bf[nf][0] = b_s[(kss + tig) * 128 + (n ^ swzB)];
                    bf[nf][1] = b_s[(kss + tig + 4) * 128 + (n ^ swzB)];
                }
#pragma unroll
                for (int mf = 0; mf < 2; mf++)
#pragma unroll
                    for (int nf = 0; nf < 4; nf++) mma8(acc[mf][nf], af[mf], bf[nf]);
            }
        }

        // ---- store z partials: g_zp[bid][row][col] ----
#pragma unroll
        for (int mf = 0; mf < 2; mf++)
#pragma unroll
            for (int nf = 0; nf < 4; nf++) {
                const int col = wn * 32 + nf * 8 + 2 * tig;
                const int mrow = wm * 32 + mf * 16 + gid;
#pragma unroll
                for (int r = 0; r < 2; r++) {
                    const int row = mrow + r * 8;
                    *(float2*)&g_zp[((size_t)bid * 128 + row) * 128 + col] =
                        make_float2(acc[mf][nf][2 * r], acc[mf][nf][2 * r + 1]);
                }
            }

        // ---- group sync (4 blocks sharing gid_n) ----
        __syncthreads();
        __threadfence();
        if (tid == 0) *(volatile unsigned*)&g_flagZ[bid * 8] = (unsigned)(t + 1);
        if (tid < 4) {
            volatile unsigned* f = &g_flagZ[(gid_n * 4 + tid) * 8];
            while (*f < (unsigned)(t + 1)) {}
        }
        __threadfence();
        __syncthreads();

        // ---- gates: batch rows [ks*32..+32) x h-cols [hc0..hc0+32) ----
        {
            float2 z[4];
#pragma unroll
            for (int g = 0; g < 4; g++) {
                float2 v = zx[g];
#pragma unroll
                for (int kp = 0; kp < 4; kp++)
                    v = add2(v, __ldcg((const float2*)(
                        g_zp + ((size_t)(gid_n * 4 + kp) * 128 + gb) * 128 + g * 32 + rc)));
                z[g] = v;
            }
            float2 hn;
            {
                const float ig = sigf(z[0].x);
                const float jg = tanhf(z[1].x);
                const float fg = sigf(z[2].x + 1.0f);   // FORGET_BIAS
                const float og = sigf(z[3].x);
                creg.x = creg.x * fg + ig * jg;
                hn.x = tanhf(creg.x) * og;
            }
            {
                const float ig = sigf(z[0].y);
                const float jg = tanhf(z[1].y);
                const float fg = sigf(z[2].y + 1.0f);
                const float og = sigf(z[3].y);
                creg.y = creg.y * fg + ig * jg;
                hn.y = tanhf(creg.y) * og;
            }
            const float2 ho = make_float2(f2tf(hn.x), f2tf(hn.y));
            *(float2*)(g_hbuf[(t + 1) & 1] + (size_t)gb * H_ + ghc) = ho;
            if (dec)
                *(float2*)(g_hs + ((size_t)st * B_ + gb) * H_ + ghc) = ho;
        }

        // ---- full barrier (flag array) ----
        __syncthreads();
        __threadfence();
        if (tid == 0) *(volatile unsigned*)&g_flagH[bid * 8] = (unsigned)(t + 1);
        if (tid < NBLK) {
            volatile unsigned* f = &g_flagH[tid * 8];
            while (*f < (unsigned)(t + 1)) __nanosleep(64);
        }
        __threadfence();
        __syncthreads();
    }
}

// ============================================================================
// mm_tf32 (R8, passing): MODE 1 (dec XG, gather), MODE 2 (projection)
// ============================================================================
#define ASTR 20
#define BSTR 136
struct TIds {
    int lane, wid, wm, wn, gid, tig;
    int ar, ak, bk, bn;
};
__device__ __forceinline__ TIds make_ids(int tid) {
    TIds s;
    s.lane = tid & 31; s.wid = tid >> 5;
    s.wm = s.wid >> 2; s.wn = s.wid & 3;
    s.gid = s.lane >> 2; s.tig = s.lane & 3;
    s.ar = tid >> 2; s.ak = (tid & 3) * 4;
    s.bk = tid >> 5; s.bn = (tid & 31) * 4;
    return s;
}
__device__ __forceinline__ void compute_bk16(
    const float* a_s, const float* b_s, const TIds& s, float acc[2][4][4])
{
#pragma unroll
    for (int ks = 0; ks < 16; ks += 8) {
        float af[2][4], bf[4][2];
#pragma unroll
        for (int mf = 0; mf < 2; mf++) {
            const int m = s.wm * 32 + mf * 16 + s.gid;
            af[mf][0] = a_s[(m)     * ASTR + ks + s.tig];
            af[mf][1] = a_s[(m + 8) * ASTR + ks + s.tig];
            af[mf][2] = a_s[(m)     * ASTR + ks + s.tig + 4];
            af[mf][3] = a_s[(m + 8) * ASTR + ks + s.tig + 4];
        }
#pragma unroll
        for (int nf = 0; nf < 4; nf++) {
            const int n = s.wn * 32 + nf * 8 + s.gid;
            bf[nf][0] = b_s[(ks + s.tig)     * BSTR + n];
            bf[nf][1] = b_s[(ks + s.tig + 4) * BSTR + n];
        }
#pragma unroll
        for (int mf = 0; mf < 2; mf++)
#pragma unroll
            for (int nf = 0; nf < 4; nf++) mma8(acc[mf][nf], af[mf], bf[nf]);
    }
}

template <int MODE>
__global__ void __launch_bounds__(512)
mm_tf32(const float* __restrict__ A, const float* __restrict__ Bm,
        const float* __restrict__ bias, float* __restrict__ Cout,
        const int* __restrict__ caption, int Kv, int ldb)
{
    __shared__ __align__(16) float a_s[2][128 * ASTR];
    __shared__ __align__(16) float b_s[2][16 * BSTR];

    const int tid = threadIdx.x;
    const TIds s = make_ids(tid);
    const int n0 = blockIdx.x * 128;
    const int mtile = blockIdx.y;

    const int m = mtile * 128 + s.ar;
    size_t aoff;
    if constexpr (MODE == 1)
        aoff = (size_t)caption[(m & 127) * L_ + (m >> 7)] * WV_;
    else
        aoff = (size_t)m * H_;
    const float* arow = ((MODE == 2) ? (const float*)g_hs : A) + aoff;

    float acc[2][4][4] = {};
    const int NK = (Kv + 15) / 16;

    auto stage = [&](int it, int buf) {
        const int kb = it * 16;
        {
            const int gk = kb + s.ak;
            float4 v = make_float4(0.f, 0.f, 0.f, 0.f);
            if (MODE != 1 || gk < Kv) v = *(const float4*)(arow + gk);
            *(float4*)&a_s[buf][s.ar * ASTR + s.ak] = tf4(v);
        }
        {
            const int gk = kb + s.bk;
            const int gn = n0 + s.bn;
            float4 v = make_float4(0.f, 0.f, 0.f, 0.f);
            const bool kok = (MODE == 1) ? (gk < Kv) : true;
            const bool nok = (MODE == 2) ? (gn < WV_) : true;
            if (kok && nok) v = *(const float4*)(Bm + (size_t)gk * ldb + gn);
            *(float4*)&b_s[buf][s.bk * BSTR + s.bn] = tf4(v);
        }
    };

    stage(0, 0);
    __syncthreads();
    int buf = 0;
    for (int it = 0; it < NK; ++it) {
        if (it + 1 < NK) stage(it + 1, buf ^ 1);
        compute_bk16(a_s[buf], b_s[buf], s, acc);
        __syncthreads();
        buf ^= 1;
    }

#pragma unroll
    for (int mf = 0; mf < 2; mf++)
#pragma unroll
        for (int nf = 0; nf < 4; nf++) {
            const int col = n0 + s.wn * 32 + nf * 8 + 2 * s.tig;
            const int mrow = mtile * 128 + s.wm * 32 + mf * 16 + s.gid;
#pragma unroll
            for (int r = 0; r < 2; r++) {
                const int row = mrow + r * 8;
                const float v0 = acc[mf][nf][2 * r];
                const float v1 = acc[mf][nf][2 * r + 1];
                if constexpr (MODE == 2) {
                    if (col < WV_) {
                        const size_t co = (size_t)((row & 127) * L_ + (row >> 7)) * WV_;
                        Cout[co + col]     = v0 + bias[col];
                        Cout[co + col + 1] = v1 + bias[col + 1];
                    }
                } else {
                    float* dst = g_xg_dec + (size_t)row * G4H + col;
                    *(float2*)dst = make_float2(v0 + bias[col], v1 + bias[col + 1]);
                }
            }
        }
}

// ---- prep kernels (R8, passing) ----
__global__ void __launch_bounds__(512)
conv_wh(const float* __restrict__ encK, const float* __restrict__ decK)
{
    const size_t i4 = ((size_t)blockIdx.x * 512 + threadIdx.x) * 4;
    if (i4 < (size_t)H_ * G4H) {
        *(float4*)&g_whE[i4] = tf4(*(const float4*)(encK + (size_t)F_  * G4H + i4));
        *(float4*)&g_whD[i4] = tf4(*(const float4*)(decK + (size_t)WV_ * G4H + i4));
    }
}

__global__ void __launch_bounds__(512)
conv_wx(const float* __restrict__ encK)
{
    const size_t i4 = ((size_t)blockIdx.x * 512 + threadIdx.x) * 4;
    if (i4 < (size_t)F_ * G4H)
        *(float4*)&g_wx[i4] = tf4(*(const float4*)(encK + i4));
}

__global__ void __launch_bounds__(512)
prep_frames(const float* __restrict__ frames)
{
    const size_t i4 = ((size_t)blockIdx.x * 512 + threadIdx.x) * 4;
    if (i4 < (size_t)4096 * F_) {
        const int m = (int)(i4 / F_), k = (int)(i4 % F_);
        const int b = m & 127, t = m >> 7;
        const float4 v = *(const float4*)(frames + ((size_t)b * T_ + t) * F_ + k);
        *(float4*)&g_frames_tf[i4] = tf4(v);
    }
}

__global__ void init_k()
{
    const int i = blockIdx.x * 256 + threadIdx.x;
    if (i < B_ * H_) g_hbuf[0][i] = 0.f;
    if (i < NBLK * 8) { g_flagZ[i] = 0u; g_flagH[i] = 0u; }
}

// ----------------------------------------------------------------------------
extern "C" void kernel_launch(void* const* d_in, const int* in_sizes, int n_in,
                              void* d_out, int out_size)
{
    const float* frames  = (const float*)d_in[0];
    const int*   caption = (const int*)  d_in[1];
    const float* emb     = (const float*)d_in[2];
    const float* encK    = (const float*)d_in[3];
    const float* encB    = (const float*)d_in[4];
    const float* decK    = (const float*)d_in[5];
    const float* decB    = (const float*)d_in[6];
    const float* projW   = (const float*)d_in[7];
    const float* projB   = (const float*)d_in[8];
    float*       out     = (float*)d_out;

    cudaFuncSetAttribute(mm0_big, cudaFuncAttributeMaxDynamicSharedMemorySize, SMEM_BIG);

    init_k<<<512, 256>>>();
    conv_wh<<<2048, 512>>>(encK, decK);
    conv_wx<<<4096, 512>>>(encK);
    prep_frames<<<4096, 512>>>(frames);

    // encoder input gates: [4096,2048] x [2048,4096] + enc_bias
    mm0_big<<<dim3(16, 32), 512, SMEM_BIG>>>(encB);

    // decoder input gates: gather(emb) [2560,300] x [300,4096] + dec_bias
    mm_tf32<1><<<dim3(32, 20), 512>>>(emb, decK, decB, nullptr, caption, WV_, G4H);

    // full recurrence (32 enc + 20 dec), R6 persistent kernel + xg preload
    lstm_persist<<<NBLK, 512>>>();

    // projection: [2560,1024] x [1024,300] + proj_b -> out[b][l][wv]
    mm_tf32<2><<<dim3(3, 20), 512>>>(nullptr, projW, projB, out, nullptr, H_, WV_);
}

// round 14
// speedup vs baseline: 1.5480x; 1.0137x over previous
#include <cuda_runtime.h>
#include <cstdint>

// ----------------------------------------------------------------------------
// B=128, T=32, F=2048, H=1024, L=20, WV=300; TF gate order i,j,f,o; FORGET_BIAS=1
// ----------------------------------------------------------------------------
#define B_   128
#define T_   32
#define F_   2048
#define H_   1024
#define L_   20
#define WV_  300
#define G4H  4096
#define NBLK 128
#define STG_WORDS 6144       // mm0_big stage: A 128x16 (2048) + B 16x256 (4096)
#define SMEM_BIG  (3 * STG_WORDS * 4)
// persist: 3 stages x (A 128x32 + B 32x128) = 3 x 8192 floats = 96KB
#define PST_STG   8192
#define SMEM_PST  (3 * PST_STG * 4)
#define PST_NK    8          // 8 x BK32 = 256 k per block (R12/R13 bug: was 4)

// ---------------- device scratch ----------------
__device__ float g_xg_enc[(size_t)4096 * 4096];   // [t*128+b][4H]
__device__ float g_xg_dec[(size_t)2560 * 4096];   // [l*128+b][4H]
__device__ float g_zp[(size_t)128 * 128 * 128];   // [bid][batch 128][gatecol 128]
__device__ float g_hbuf[2][B_ * H_];              // double-buffered h (tf32-rounded)
__device__ float g_hs[(size_t)L_ * B_ * H_];      // decoder outputs
__device__ float g_whE[(size_t)H_ * G4H];         // tf32-rounded Wh (encoder)
__device__ float g_whD[(size_t)H_ * G4H];         // tf32-rounded Wh (decoder)
__device__ float g_wx[(size_t)F_ * G4H];          // tf32-rounded Wx (encoder, [k][n])
__device__ float g_frames_tf[(size_t)4096 * F_];  // [m=t*128+b][k] tf32 frames
__device__ unsigned g_flagZ[NBLK * 8];
__device__ unsigned g_flagH[NBLK * 8];

// ---------------- helpers ----------------
__device__ __forceinline__ float f2tf(float x) {
    unsigned u;
    asm("cvt.rna.tf32.f32 %0, %1;" : "=r"(u) : "f"(x));
    return __uint_as_float(u);
}
__device__ __forceinline__ float4 tf4(float4 v) {
    return make_float4(f2tf(v.x), f2tf(v.y), f2tf(v.z), f2tf(v.w));
}
__device__ __forceinline__ void mma8(float* c, const float* a, const float* b) {
    asm volatile(
        "mma.sync.aligned.m16n8k8.row.col.f32.tf32.tf32.f32 "
        "{%0,%1,%2,%3},{%4,%5,%6,%7},{%8,%9},{%0,%1,%2,%3};"
        : "+f"(c[0]), "+f"(c[1]), "+f"(c[2]), "+f"(c[3])
        : "r"(__float_as_uint(a[0])), "r"(__float_as_uint(a[1])),
          "r"(__float_as_uint(a[2])), "r"(__float_as_uint(a[3])),
          "r"(__float_as_uint(b[0])), "r"(__float_as_uint(b[1])));
}
__device__ __forceinline__ float2 add2(float2 a, float2 b) {
    a.x += b.x; a.y += b.y; return a;
}
__device__ __forceinline__ float sigf(float x) { return 1.f / (1.f + __expf(-x)); }

__device__ __forceinline__ uint32_t smem_u32(const void* p) {
    return (uint32_t)__cvta_generic_to_shared(p);
}
__device__ __forceinline__ void cpa16(uint32_t dst, const void* src) {
    asm volatile("cp.async.cg.shared.global [%0], [%1], 16;" :: "r"(dst), "l"(src));
}
#define CP_COMMIT() asm volatile("cp.async.commit_group;")
#define CP_WAIT1()  asm volatile("cp.async.wait_group 1;")

// ============================================================================
// mm0_big (R8/R11, measured ~132 TF/s): enc XG GEMM, tile 128x256, BK=16.
// ============================================================================
struct CoreIds {
    int lane, wid, wm, wn, gid, tig, swzA;
    int ar, akq, a_dst;
    int bk, bn, b_dst;
};
__device__ __forceinline__ CoreIds core_ids(int tid) {
    CoreIds s;
    s.lane = tid & 31; s.wid = tid >> 5;
    s.wm = s.wid >> 2; s.wn = s.wid & 3;
    s.gid = s.lane >> 2; s.tig = s.lane & 3;
    s.swzA = ((s.gid >> 1) & 3) << 2;
    s.ar = tid >> 2; s.akq = (tid & 3) << 2;
    s.a_dst = s.ar * 16 + (s.akq ^ (((s.ar >> 1) & 3) << 2));
    s.bk = tid >> 5; s.bn = (tid & 31) * 8;
    s.b_dst = 2048 + s.bk * 256 + (s.bn ^ ((s.bk & 3) << 3));
    return s;
}

__device__ __forceinline__ void core_compute(
    const float* __restrict__ a_s, const float* __restrict__ b_s,
    const CoreIds& s, float acc[2][8][4])
{
#pragma unroll
    for (int ks = 0; ks < 16; ks += 8) {
        float af[2][4], bf[8][2];
#pragma unroll
        for (int mf = 0; mf < 2; mf++) {
            const int m0 = s.wm * 32 + mf * 16 + s.gid;
            const int c0 = (ks + s.tig) ^ s.swzA;
            const int c1 = (ks + s.tig + 4) ^ s.swzA;
            af[mf][0] = a_s[m0 * 16 + c0];
            af[mf][1] = a_s[(m0 + 8) * 16 + c0];
            af[mf][2] = a_s[m0 * 16 + c1];
            af[mf][3] = a_s[(m0 + 8) * 16 + c1];
        }
#pragma unroll
        for (int nf = 0; nf < 8; nf++) {
            const int n = (s.wn * 64 + nf * 8 + s.gid) ^ (s.tig << 3);
            bf[nf][0] = b_s[(ks + s.tig) * 256 + n];
            bf[nf][1] = b_s[(ks + s.tig + 4) * 256 + n];
        }
#pragma unroll
        for (int mf = 0; mf < 2; mf++)
#pragma unroll
            for (int nf = 0; nf < 8; nf++) mma8(acc[mf][nf], af[mf], bf[nf]);
    }
}

__global__ void __launch_bounds__(512)
mm0_big(const float* __restrict__ bias)
{
    extern __shared__ float dsm[];
    const int tid = threadIdx.x;
    const CoreIds s = core_ids(tid);
    const uint32_t smb = smem_u32(dsm);
    const int ntile = blockIdx.x, mtile = blockIdx.y;

    const float* arow = g_frames_tf + (size_t)(mtile * 128 + s.ar) * F_;
    const float* bsrc = g_wx + ntile * 256 + s.bn;

    float acc[2][8][4] = {};
    const int NK = F_ / 16;

    auto issue = [&](int st) {
        const uint32_t sb = smb + (uint32_t)((st % 3) * STG_WORDS) * 4;
        const int kb = st * 16;
        cpa16(sb + s.a_dst * 4, arow + kb + s.akq);
        const float* bp = bsrc + (size_t)(kb + s.bk) * G4H;
        cpa16(sb + s.b_dst * 4, bp);
        cpa16(sb + (s.b_dst + 4) * 4, bp + 4);
    };

    issue(0); CP_COMMIT();
    issue(1); CP_COMMIT();

    for (int kt = 0; kt < NK; ++kt) {
        CP_WAIT1();
        __syncthreads();
        if (kt + 2 < NK) issue(kt + 2);
        CP_COMMIT();
        const float* a_s = dsm + (kt % 3) * STG_WORDS;
        core_compute(a_s, a_s + 2048, s, acc);
    }

#pragma unroll
    for (int mf = 0; mf < 2; mf++)
#pragma unroll
        for (int nf = 0; nf < 8; nf++) {
            const int col = ntile * 256 + s.wn * 64 + nf * 8 + 2 * s.tig;
            const float2 bb = *(const float2*)(bias + col);
#pragma unroll
            for (int r = 0; r < 2; r++) {
                const int row = mtile * 128 + s.wm * 32 + mf * 16 + s.gid + r * 8;
                *(float2*)&g_xg_enc[(size_t)row * G4H + col] =
                    make_float2(acc[mf][nf][2 * r] + bb.x,
                                acc[mf][nf][2 * r + 1] + bb.y);
            }
        }
}

// ============================================================================
// Persistent recurrence: R11 sync protocol (full barrier + group sync, single
// zp buffer, double h buffer) + BK=32 pipeline, 8 rounds/step (FIXED: R12/R13
// ran only 4 rounds = half the k-range). Arithmetic bit-identical to R11.
// ============================================================================
__global__ void __launch_bounds__(512)
lstm_persist()
{
    extern __shared__ float dsm[];   // 3 stages x [A0 2048|A1 2048|B0 2048|B1 2048]
    const int tid = threadIdx.x, bid = blockIdx.x;
    const int g = bid >> 2, ks = bid & 3;
    const int hc0 = g * 32;
    const int k0 = ks * 256;

    const int lane = tid & 31, wid = tid >> 5;
    const int wm = wid >> 2, wn = wid & 3;
    const int gid = lane >> 2, tig = lane & 3;
    const int swzA = ((gid >> 1) & 3) << 2;
    const int swzB = tig * 8;

    const int ar = tid >> 2, akq = (tid & 3) * 4;
    const int a_dst = ar * 16 + (akq ^ (((ar >> 1) & 3) << 2));
    const int bk = tid >> 5, bseg = (tid & 31) >> 3, bnn = (tid & 7) * 4;
    const int b_dst = bk * 128 + ((bseg * 32 + bnn) ^ ((bk & 3) * 8));
    const size_t b_srcoff = (size_t)bk * G4H + bseg * 1024 + hc0 + bnn;

    const uint32_t smb = smem_u32(dsm);

    // gate ids: thread owns 2 elements (gb, ghc), (gb, ghc+1)
    const int li = tid * 2, rb = li >> 5, rc = li & 31;
    const int gb = ks * 32 + rb;
    const int ghc = hc0 + rc;
    float2 creg = make_float2(0.f, 0.f);

    for (int t = 0; t < T_ + L_; ++t) {
        const bool dec = (t >= T_);
        const int st = dec ? t - T_ : t;
        const float* wh = dec ? g_whD : g_whE;
        const float* hsrc = g_hbuf[t & 1];
        const float* xg = (dec ? g_xg_dec : g_xg_enc) + (size_t)st * (B_ * G4H);

        // preload xg gate inputs (latency hidden under GEMM)
        float2 zx[4];
#pragma unroll
        for (int gt = 0; gt < 4; gt++)
            zx[gt] = *(const float2*)(xg + (size_t)gb * G4H + gt * 1024 + ghc);

        float acc[2][4][4] = {};

        auto issue = [&](int kt32) {
            const uint32_t sb = smb + (uint32_t)((kt32 % 3) * PST_STG) * 4;
            const int kb = k0 + kt32 * 32;
#pragma unroll
            for (int h = 0; h < 2; h++) {
                cpa16(sb + (h * 2048 + a_dst) * 4,
                      hsrc + (size_t)ar * H_ + kb + h * 16 + akq);
                cpa16(sb + (4096 + h * 2048 + b_dst) * 4,
                      wh + (size_t)(kb + h * 16) * G4H + b_srcoff);
            }
        };

        issue(0); CP_COMMIT();
        issue(1); CP_COMMIT();

        for (int kt = 0; kt < PST_NK; ++kt) {
            CP_WAIT1();
            __syncthreads();
            if (kt + 2 < PST_NK) issue(kt + 2);
            CP_COMMIT();

            const float* base = dsm + (kt % 3) * PST_STG;
#pragma unroll
            for (int h = 0; h < 2; h++) {
                const float* a_s = base + h * 2048;
                const float* b_s = base + 4096 + h * 2048;
#pragma unroll
                for (int kss = 0; kss < 16; kss += 8) {
                    float af[2][4], bf[4][2];
#pragma unroll
                    for (int mf = 0; mf < 2; mf++) {
                        const int m0 = wm * 32 + mf * 16 + gid;
                        const int c0 = (kss + tig) ^ swzA;
                        const int c1 = (kss + tig + 4) ^ swzA;
                        af[mf][0] = a_s[m0 * 16 + c0];
                        af[mf][1] = a_s[(m0 + 8) * 16 + c0];
                        af[mf][2] = a_s[m0 * 16 + c1];
                        af[mf][3] = a_s[(m0 + 8) * 16 + c1];
                    }
#pragma unroll
                    for (int nf = 0; nf < 4; nf++) {
                        const int n = wn * 32 + nf * 8 + gid;
                        bf[nf][0] = b_s[(kss + tig) * 128 + (n ^ swzB)];
                        bf[nf][1] = b_s[(kss + tig + 4) * 128 + (n ^ swzB)];
                    }
#pragma unroll
                    for (int mf = 0; mf < 2; mf++)
#pragma unroll
                        for (int nf = 0; nf < 4; nf++)
                            mma8(acc[mf][nf], af[mf], bf[nf]);
                }
            }
        }

        // ---- store z partials: g_zp[bid][row][col] ----
#pragma unroll
        for (int mf = 0; mf < 2; mf++)
#pragma unroll
            for (int nf = 0; nf < 4; nf++) {
                const int col = wn * 32 + nf * 8 + 2 * tig;
                const int mrow = wm * 32 + mf * 16 + gid;
#pragma unroll
                for (int r = 0; r < 2; r++) {
                    const int row = mrow + r * 8;
                    *(float2*)&g_zp[((size_t)bid * 128 + row) * 128 + col] =
                        make_float2(acc[mf][nf][2 * r], acc[mf][nf][2 * r + 1]);
                }
            }

        // ---- group sync (4 k-split blocks of this n-group) ----
        __syncthreads();
        __threadfence();
        if (tid == 0) *(volatile unsigned*)&g_flagZ[bid * 8] = (unsigned)(t + 1);
        if (tid < 4) {
            volatile unsigned* f = &g_flagZ[(g * 4 + tid) * 8];
            while (*f < (unsigned)(t + 1)) {}
        }
        __threadfence();
        __syncthreads();

        // ---- gates: batch rows [ks*32..+32) x h-cols [hc0..hc0+32) ----
        {
            float2 z[4];
#pragma unroll
            for (int gt = 0; gt < 4; gt++) {
                float2 v = zx[gt];
#pragma unroll
                for (int kp = 0; kp < 4; kp++)
                    v = add2(v, __ldcg((const float2*)(
                        g_zp + ((size_t)(g * 4 + kp) * 128 + gb) * 128 + gt * 32 + rc)));
                z[gt] = v;
            }
            float2 hn;
            {
                const float ig = sigf(z[0].x);
                const float jg = tanhf(z[1].x);
                const float fg = sigf(z[2].x + 1.0f);   // FORGET_BIAS
                const float og = sigf(z[3].x);
                creg.x = creg.x * fg + ig * jg;
                hn.x = tanhf(creg.x) * og;
            }
            {
                const float ig = sigf(z[0].y);
                const float jg = tanhf(z[1].y);
                const float fg = sigf(z[2].y + 1.0f);
                const float og = sigf(z[3].y);
                creg.y = creg.y * fg + ig * jg;
                hn.y = tanhf(creg.y) * og;
            }
            const float2 ho = make_float2(f2tf(hn.x), f2tf(hn.y));
            *(float2*)(g_hbuf[(t + 1) & 1] + (size_t)gb * H_ + ghc) = ho;
            if (dec)
                *(float2*)(g_hs + ((size_t)st * B_ + gb) * H_ + ghc) = ho;
        }

        // ---- full barrier (flag array) ----
        __syncthreads();
        __threadfence();
        if (tid == 0) *(volatile unsigned*)&g_flagH[bid * 8] = (unsigned)(t + 1);
        if (tid < NBLK) {
            volatile unsigned* f = &g_flagH[tid * 8];
            while (*f < (unsigned)(t + 1)) __nanosleep(64);
        }
        __threadfence();
        __syncthreads();
    }
}

// ============================================================================
// mm_tf32 (R8, passing): MODE 1 (dec XG, gather), MODE 2 (projection)
// ============================================================================
#define ASTR 20
#define BSTR 136
struct TIds {
    int lane, wid, wm, wn, gid, tig;
    int ar, ak, bk, bn;
};
__device__ __forceinline__ TIds make_ids(int tid) {
    TIds s;
    s.lane = tid & 31; s.wid = tid >> 5;
    s.wm = s.wid >> 2; s.wn = s.wid & 3;
    s.gid = s.lane >> 2; s.tig = s.lane & 3;
    s.ar = tid >> 2; s.ak = (tid & 3) * 4;
    s.bk = tid >> 5; s.bn = (tid & 31) * 4;
    return s;
}
__device__ __forceinline__ void compute_bk16(
    const float* a_s, const float* b_s, const TIds& s, float acc[2][4][4])
{
#pragma unroll
    for (int ks = 0; ks < 16; ks += 8) {
        float af[2][4], bf[4][2];
#pragma unroll
        for (int mf = 0; mf < 2; mf++) {
            const int m = s.wm * 32 + mf * 16 + s.gid;
            af[mf][0] = a_s[(m)     * ASTR + ks + s.tig];
            af[mf][1] = a_s[(m + 8) * ASTR + ks + s.tig];
            af[mf][2] = a_s[(m)     * ASTR + ks + s.tig + 4];
            af[mf][3] = a_s[(m + 8) * ASTR + ks + s.tig + 4];
        }
#pragma unroll
        for (int nf = 0; nf < 4; nf++) {
            const int n = s.wn * 32 + nf * 8 + s.gid;
            bf[nf][0] = b_s[(ks + s.tig)     * BSTR + n];
            bf[nf][1] = b_s[(ks + s.tig + 4) * BSTR + n];
        }
#pragma unroll
        for (int mf = 0; mf < 2; mf++)
#pragma unroll
            for (int nf = 0; nf < 4; nf++) mma8(acc[mf][nf], af[mf], bf[nf]);
    }
}

template <int MODE>
__global__ void __launch_bounds__(512)
mm_tf32(const float* __restrict__ A, const float* __restrict__ Bm,
        const float* __restrict__ bias, float* __restrict__ Cout,
        const int* __restrict__ caption, int Kv, int ldb)
{
    __shared__ __align__(16) float a_s[2][128 * ASTR];
    __shared__ __align__(16) float b_s[2][16 * BSTR];

    const int tid = threadIdx.x;
    const TIds s = make_ids(tid);
    const int n0 = blockIdx.x * 128;
    const int mtile = blockIdx.y;

    const int m = mtile * 128 + s.ar;
    size_t aoff;
    if constexpr (MODE == 1)
        aoff = (size_t)caption[(m & 127) * L_ + (m >> 7)] * WV_;
    else
        aoff = (size_t)m * H_;
    const float* arow = ((MODE == 2) ? (const float*)g_hs : A) + aoff;

    float acc[2][4][4] = {};
    const int NK = (Kv + 15) / 16;

    auto stage = [&](int it, int buf) {
        const int kb = it * 16;
        {
            const int gk = kb + s.ak;
            float4 v = make_float4(0.f, 0.f, 0.f, 0.f);
            if (MODE != 1 || gk < Kv) v = *(const float4*)(arow + gk);
            *(float4*)&a_s[buf][s.ar * ASTR + s.ak] = tf4(v);
        }
        {
            const int gk = kb + s.bk;
            const int gn = n0 + s.bn;
            float4 v = make_float4(0.f, 0.f, 0.f, 0.f);
            const bool kok = (MODE == 1) ? (gk < Kv) : true;
            const bool nok = (MODE == 2) ? (gn < WV_) : true;
            if (kok && nok) v = *(const float4*)(Bm + (size_t)gk * ldb + gn);
            *(float4*)&b_s[buf][s.bk * BSTR + s.bn] = tf4(v);
        }
    };

    stage(0, 0);
    __syncthreads();
    int buf = 0;
    for (int it = 0; it < NK; ++it) {
        if (it + 1 < NK) stage(it + 1, buf ^ 1);
        compute_bk16(a_s[buf], b_s[buf], s, acc);
        __syncthreads();
        buf ^= 1;
    }

#pragma unroll
    for (int mf = 0; mf < 2; mf++)
#pragma unroll
        for (int nf = 0; nf < 4; nf++) {
            const int col = n0 + s.wn * 32 + nf * 8 + 2 * s.tig;
            const int mrow = mtile * 128 + s.wm * 32 + mf * 16 + s.gid;
#pragma unroll
            for (int r = 0; r < 2; r++) {
                const int row = mrow + r * 8;
                const float v0 = acc[mf][nf][2 * r];
                const float v1 = acc[mf][nf][2 * r + 1];
                if constexpr (MODE == 2) {
                    if (col < WV_) {
                        const size_t co = (size_t)((row & 127) * L_ + (row >> 7)) * WV_;
                        Cout[co + col]     = v0 + bias[col];
                        Cout[co + col + 1] = v1 + bias[col + 1];
                    }
                } else {
                    float* dst = g_xg_dec + (size_t)row * G4H + col;
                    *(float2*)dst = make_float2(v0 + bias[col], v1 + bias[col + 1]);
                }
            }
        }
}

// ---- prep kernels (R8, passing) ----
__global__ void __launch_bounds__(512)
conv_wh(const float* __restrict__ encK, const float* __restrict__ decK)
{
    const size_t i4 = ((size_t)blockIdx.x * 512 + threadIdx.x) * 4;
    if (i4 < (size_t)H_ * G4H) {
        *(float4*)&g_whE[i4] = tf4(*(const float4*)(encK + (size_t)F_  * G4H + i4));
        *(float4*)&g_whD[i4] = tf4(*(const float4*)(decK + (size_t)WV_ * G4H + i4));
    }
}

__global__ void __launch_bounds__(512)
conv_wx(const float* __restrict__ encK)
{
    const size_t i4 = ((size_t)blockIdx.x * 512 + threadIdx.x) * 4;
    if (i4 < (size_t)F_ * G4H)
        *(float4*)&g_wx[i4] = tf4(*(const float4*)(encK + i4));
}

__global__ void __launch_bounds__(512)
prep_frames(const float* __restrict__ frames)
{
    const size_t i4 = ((size_t)blockIdx.x * 512 + threadIdx.x) * 4;
    if (i4 < (size_t)4096 * F_) {
        const int m = (int)(i4 / F_), k = (int)(i4 % F_);
        const int b = m & 127, t = m >> 7;
        const float4 v = *(const float4*)(frames + ((size_t)b * T_ + t) * F_ + k);
        *(float4*)&g_frames_tf[i4] = tf4(v);
    }
}

__global__ void init_k()
{
    const int i = blockIdx.x * 256 + threadIdx.x;
    if (i < B_ * H_) g_hbuf[0][i] = 0.f;
    if (i < NBLK * 8) { g_flagZ[i] = 0u; g_flagH[i] = 0u; }
}

// ----------------------------------------------------------------------------
extern "C" void kernel_launch(void* const* d_in, const int* in_sizes, int n_in,
                              void* d_out, int out_size)
{
    const float* frames  = (const float*)d_in[0];
    const int*   caption = (const int*)  d_in[1];
    const float* emb     = (const float*)d_in[2];
    const float* encK    = (const float*)d_in[3];
    const float* encB    = (const float*)d_in[4];
    const float* decK    = (const float*)d_in[5];
    const float* decB    = (const float*)d_in[6];
    const float* projW   = (const float*)d_in[7];
    const float* projB   = (const float*)d_in[8];
    float*       out     = (float*)d_out;

    cudaFuncSetAttribute(mm0_big, cudaFuncAttributeMaxDynamicSharedMemorySize, SMEM_BIG);
    cudaFuncSetAttribute(lstm_persist, cudaFuncAttributeMaxDynamicSharedMemorySize, SMEM_PST);

    init_k<<<512, 256>>>();
    conv_wh<<<2048, 512>>>(encK, decK);
    conv_wx<<<4096, 512>>>(encK);
    prep_frames<<<4096, 512>>>(frames);

    // encoder input gates: [4096,2048] x [2048,4096] + enc_bias
    mm0_big<<<dim3(16, 32), 512, SMEM_BIG>>>(encB);

    // decoder input gates: gather(emb) [2560,300] x [300,4096] + dec_bias
    mm_tf32<1><<<dim3(32, 20), 512>>>(emb, decK, decB, nullptr, caption, WV_, G4H);

    // full recurrence (32 enc + 20 dec): R11 sync + BK=32 pipeline (8 rounds)
    lstm_persist<<<NBLK, 512, SMEM_PST>>>();

    // projection: [2560,1024] x [1024,300] + proj_b -> out[b][l][wv]
    mm_tf32<2><<<dim3(3, 20), 512>>>(nullptr, projW, projB, out, nullptr, H_, WV_);
}

// round 15
// speedup vs baseline: 1.5965x; 1.0313x over previous
#include <cuda_runtime.h>
#include <cstdint>

// ----------------------------------------------------------------------------
// B=128, T=32, F=2048, H=1024, L=20, WV=300; TF gate order i,j,f,o; FORGET_BIAS=1
// ----------------------------------------------------------------------------
#define B_   128
#define T_   32
#define F_   2048
#define H_   1024
#define L_   20
#define WV_  300
#define G4H  4096
#define NBLK 128
#define STG_WORDS 6144       // mm0_big stage: A 128x16 (2048) + B 16x256 (4096)
#define SMEM_BIG  (3 * STG_WORDS * 4)
// persist: 3 stages x (A 128x32 + B 32x128) = 3 x 8192 floats = 96KB
#define PST_STG   8192
#define SMEM_PST  (3 * PST_STG * 4)
#define PST_NK    8          // 8 x BK32 = 256 k per block
#define ZPSZ      ((size_t)128 * 128 * 128)

// ---------------- device scratch ----------------
__device__ float g_xg_enc[(size_t)4096 * 4096];   // [t*128+b][4H]
__device__ float g_xg_dec[(size_t)2560 * 4096];   // [l*128+b][4H]
__device__ float g_zp[2 * ZPSZ];                  // [t&1][bid][batch 128][col 128]
__device__ float g_hbuf[3][B_ * H_];              // triple-buffered h (tf32-rounded)
__device__ float g_hs[(size_t)L_ * B_ * H_];      // decoder outputs
__device__ float g_whE[(size_t)H_ * G4H];         // tf32-rounded Wh (encoder)
__device__ float g_whD[(size_t)H_ * G4H];         // tf32-rounded Wh (decoder)
__device__ float g_wx[(size_t)F_ * G4H];          // tf32-rounded Wx (encoder, [k][n])
__device__ float g_frames_tf[(size_t)4096 * F_];  // [m=t*128+b][k] tf32 frames
__device__ unsigned g_flagZ[NBLK * 8];            // zp-ready (value = t+1)
__device__ unsigned g_flagH[NBLK * 8];            // gates-done (value = t+1)

// ---------------- helpers ----------------
__device__ __forceinline__ float f2tf(float x) {
    unsigned u;
    asm("cvt.rna.tf32.f32 %0, %1;" : "=r"(u) : "f"(x));
    return __uint_as_float(u);
}
__device__ __forceinline__ float4 tf4(float4 v) {
    return make_float4(f2tf(v.x), f2tf(v.y), f2tf(v.z), f2tf(v.w));
}
__device__ __forceinline__ void mma8(float* c, const float* a, const float* b) {
    asm volatile(
        "mma.sync.aligned.m16n8k8.row.col.f32.tf32.tf32.f32 "
        "{%0,%1,%2,%3},{%4,%5,%6,%7},{%8,%9},{%0,%1,%2,%3};"
        : "+f"(c[0]), "+f"(c[1]), "+f"(c[2]), "+f"(c[3])
        : "r"(__float_as_uint(a[0])), "r"(__float_as_uint(a[1])),
          "r"(__float_as_uint(a[2])), "r"(__float_as_uint(a[3])),
          "r"(__float_as_uint(b[0])), "r"(__float_as_uint(b[1])));
}
__device__ __forceinline__ float2 add2(float2 a, float2 b) {
    a.x += b.x; a.y += b.y; return a;
}
__device__ __forceinline__ float sigf(float x) { return 1.f / (1.f + __expf(-x)); }

__device__ __forceinline__ uint32_t smem_u32(const void* p) {
    return (uint32_t)__cvta_generic_to_shared(p);
}
__device__ __forceinline__ void cpa16(uint32_t dst, const void* src) {
    asm volatile("cp.async.cg.shared.global [%0], [%1], 16;" :: "r"(dst), "l"(src));
}
#define CP_COMMIT() asm volatile("cp.async.commit_group;")
#define CP_WAIT1()  asm volatile("cp.async.wait_group 1;")

// ============================================================================
// mm0_big (R8/R11/R14, measured ~132 TF/s): enc XG GEMM, tile 128x256, BK=16.
// ============================================================================
struct CoreIds {
    int lane, wid, wm, wn, gid, tig, swzA;
    int ar, akq, a_dst;
    int bk, bn, b_dst;
};
__device__ __forceinline__ CoreIds core_ids(int tid) {
    CoreIds s;
    s.lane = tid & 31; s.wid = tid >> 5;
    s.wm = s.wid >> 2; s.wn = s.wid & 3;
    s.gid = s.lane >> 2; s.tig = s.lane & 3;
    s.swzA = ((s.gid >> 1) & 3) << 2;
    s.ar = tid >> 2; s.akq = (tid & 3) << 2;
    s.a_dst = s.ar * 16 + (s.akq ^ (((s.ar >> 1) & 3) << 2));
    s.bk = tid >> 5; s.bn = (tid & 31) * 8;
    s.b_dst = 2048 + s.bk * 256 + (s.bn ^ ((s.bk & 3) << 3));
    return s;
}

__device__ __forceinline__ void core_compute(
    const float* __restrict__ a_s, const float* __restrict__ b_s,
    const CoreIds& s, float acc[2][8][4])
{
#pragma unroll
    for (int ks = 0; ks < 16; ks += 8) {
        float af[2][4], bf[8][2];
#pragma unroll
        for (int mf = 0; mf < 2; mf++) {
            const int m0 = s.wm * 32 + mf * 16 + s.gid;
            const int c0 = (ks + s.tig) ^ s.swzA;
            const int c1 = (ks + s.tig + 4) ^ s.swzA;
            af[mf][0] = a_s[m0 * 16 + c0];
            af[mf][1] = a_s[(m0 + 8) * 16 + c0];
            af[mf][2] = a_s[m0 * 16 + c1];
            af[mf][3] = a_s[(m0 + 8) * 16 + c1];
        }
#pragma unroll
        for (int nf = 0; nf < 8; nf++) {
            const int n = (s.wn * 64 + nf * 8 + s.gid) ^ (s.tig << 3);
            bf[nf][0] = b_s[(ks + s.tig) * 256 + n];
            bf[nf][1] = b_s[(ks + s.tig + 4) * 256 + n];
        }
#pragma unroll
        for (int mf = 0; mf < 2; mf++)
#pragma unroll
            for (int nf = 0; nf < 8; nf++) mma8(acc[mf][nf], af[mf], bf[nf]);
    }
}

__global__ void __launch_bounds__(512)
mm0_big(const float* __restrict__ bias)
{
    extern __shared__ float dsm[];
    const int tid = threadIdx.x;
    const CoreIds s = core_ids(tid);
    const uint32_t smb = smem_u32(dsm);
    const int ntile = blockIdx.x, mtile = blockIdx.y;

    const float* arow = g_frames_tf + (size_t)(mtile * 128 + s.ar) * F_;
    const float* bsrc = g_wx + ntile * 256 + s.bn;

    float acc[2][8][4] = {};
    const int NK = F_ / 16;

    auto issue = [&](int st) {
        const uint32_t sb = smb + (uint32_t)((st % 3) * STG_WORDS) * 4;
        const int kb = st * 16;
        cpa16(sb + s.a_dst * 4, arow + kb + s.akq);
        const float* bp = bsrc + (size_t)(kb + s.bk) * G4H;
        cpa16(sb + s.b_dst * 4, bp);
        cpa16(sb + (s.b_dst + 4) * 4, bp + 4);
    };

    issue(0); CP_COMMIT();
    issue(1); CP_COMMIT();

    for (int kt = 0; kt < NK; ++kt) {
        CP_WAIT1();
        __syncthreads();
        if (kt + 2 < NK) issue(kt + 2);
        CP_COMMIT();
        const float* a_s = dsm + (kt % 3) * STG_WORDS;
        core_compute(a_s, a_s + 2048, s, acc);
    }

#pragma unroll
    for (int mf = 0; mf < 2; mf++)
#pragma unroll
        for (int nf = 0; nf < 8; nf++) {
            const int col = ntile * 256 + s.wn * 64 + nf * 8 + 2 * s.tig;
            const float2 bb = *(const float2*)(bias + col);
#pragma unroll
            for (int r = 0; r < 2; r++) {
                const int row = mtile * 128 + s.wm * 32 + mf * 16 + s.gid + r * 8;
                *(float2*)&g_xg_enc[(size_t)row * G4H + col] =
                    make_float2(acc[mf][nf][2 * r] + bb.x,
                                acc[mf][nf][2 * r + 1] + bb.y);
            }
        }
}

// ============================================================================
// Persistent recurrence: R14 GEMM (BK=32, 8 rounds — verified) + relaxed sync:
// block (g,ks) waits only on the 32 producers of its h k-range. h triple-
// buffered, zp double-buffered; two-hop producer closure covers all 128
// blocks, protecting buffer reuse. Arithmetic bit-identical to R14.
// ============================================================================
__global__ void __launch_bounds__(512)
lstm_persist()
{
    extern __shared__ float dsm[];   // 3 stages x [A0 2048|A1 2048|B0 2048|B1 2048]
    const int tid = threadIdx.x, bid = blockIdx.x;
    const int g = bid >> 2, ks = bid & 3;
    const int hc0 = g * 32;
    const int k0 = ks * 256;

    const int lane = tid & 31, wid = tid >> 5;
    const int wm = wid >> 2, wn = wid & 3;
    const int gid = lane >> 2, tig = lane & 3;
    const int swzA = ((gid >> 1) & 3) << 2;
    const int swzB = tig * 8;

    const int ar = tid >> 2, akq = (tid & 3) * 4;
    const int a_dst = ar * 16 + (akq ^ (((ar >> 1) & 3) << 2));
    const int bk = tid >> 5, bseg = (tid & 31) >> 3, bnn = (tid & 7) * 4;
    const int b_dst = bk * 128 + ((bseg * 32 + bnn) ^ ((bk & 3) * 8));
    const size_t b_srcoff = (size_t)bk * G4H + bseg * 1024 + hc0 + bnn;

    const uint32_t smb = smem_u32(dsm);

    // gate ids: thread owns 2 elements (gb, ghc), (gb, ghc+1)
    const int li = tid * 2, rb = li >> 5, rc = li & 31;
    const int gb = ks * 32 + rb;
    const int ghc = hc0 + rc;
    float2 creg = make_float2(0.f, 0.f);

    for (int t = 0; t < T_ + L_; ++t) {
        const bool dec = (t >= T_);
        const int st = dec ? t - T_ : t;
        const float* wh = dec ? g_whD : g_whE;
        const float* hsrc = g_hbuf[t % 3];
        const float* xg = (dec ? g_xg_dec : g_xg_enc) + (size_t)st * (B_ * G4H);
        float* zp = g_zp + (size_t)(t & 1) * ZPSZ;

        // preload xg gate inputs (latency hidden under GEMM)
        float2 zx[4];
#pragma unroll
        for (int gt = 0; gt < 4; gt++)
            zx[gt] = *(const float2*)(xg + (size_t)gb * G4H + gt * 1024 + ghc);

        // ---- wait only on the 32 producers of h cols [k0, k0+256) ----
        if (t > 0) {
            if (tid < 32) {
                volatile unsigned* f = &g_flagH[(ks * 32 + tid) * 8];
                while (*f < (unsigned)t) {}
            }
            __threadfence();
            __syncthreads();
        }

        float acc[2][4][4] = {};

        auto issue = [&](int kt32) {
            const uint32_t sb = smb + (uint32_t)((kt32 % 3) * PST_STG) * 4;
            const int kb = k0 + kt32 * 32;
#pragma unroll
            for (int h = 0; h < 2; h++) {
                cpa16(sb + (h * 2048 + a_dst) * 4,
                      hsrc + (size_t)ar * H_ + kb + h * 16 + akq);
                cpa16(sb + (4096 + h * 2048 + b_dst) * 4,
                      wh + (size_t)(kb + h * 16) * G4H + b_srcoff);
            }
        };

        issue(0); CP_COMMIT();
        issue(1); CP_COMMIT();

        for (int kt = 0; kt < PST_NK; ++kt) {
            CP_WAIT1();
            __syncthreads();
            if (kt + 2 < PST_NK) issue(kt + 2);
            CP_COMMIT();

            const float* base = dsm + (kt % 3) * PST_STG;
#pragma unroll
            for (int h = 0; h < 2; h++) {
                const float* a_s = base + h * 2048;
                const float* b_s = base + 4096 + h * 2048;
#pragma unroll
                for (int kss = 0; kss < 16; kss += 8) {
                    float af[2][4], bf[4][2];
#pragma unroll
                    for (int mf = 0; mf < 2; mf++) {
                        const int m0 = wm * 32 + mf * 16 + gid;
                        const int c0 = (kss + tig) ^ swzA;
                        const int c1 = (kss + tig + 4) ^ swzA;
                        af[mf][0] = a_s[m0 * 16 + c0];
                        af[mf][1] = a_s[(m0 + 8) * 16 + c0];
                        af[mf][2] = a_s[m0 * 16 + c1];
                        af[mf][3] = a_s[(m0 + 8) * 16 + c1];
                    }
#pragma unroll
                    for (int nf = 0; nf < 4; nf++) {
                        const int n = wn * 32 + nf * 8 + gid;
                        bf[nf][0] = b_s[(kss + tig) * 128 + (n ^ swzB)];
                        bf[nf][1] = b_s[(kss + tig + 4) * 128 + (n ^ swzB)];
                    }
#pragma unroll
                    for (int mf = 0; mf < 2; mf++)
#pragma unroll
                        for (int nf = 0; nf < 4; nf++)
                            mma8(acc[mf][nf], af[mf], bf[nf]);
                }
            }
        }

        // ---- store z partials: zp[bid][row][col] ----
#pragma unroll
        for (int mf = 0; mf < 2; mf++)
#pragma unroll
            for (int nf = 0; nf < 4; nf++) {
                const int col = wn * 32 + nf * 8 + 2 * tig;
                const int mrow = wm * 32 + mf * 16 + gid;
#pragma unroll
                for (int r = 0; r < 2; r++) {
                    const int row = mrow + r * 8;
                    *(float2*)&zp[((size_t)bid * 128 + row) * 128 + col] =
                        make_float2(acc[mf][nf][2 * r], acc[mf][nf][2 * r + 1]);
                }
            }

        // ---- group sync (4 k-split blocks of this n-group) ----
        __syncthreads();
        __threadfence();
        if (tid == 0) *(volatile unsigned*)&g_flagZ[bid * 8] = (unsigned)(t + 1);
        if (tid < 4) {
            volatile unsigned* f = &g_flagZ[(g * 4 + tid) * 8];
            while (*f < (unsigned)(t + 1)) {}
        }
        __threadfence();
        __syncthreads();

        // ---- gates: batch rows [ks*32..+32) x h-cols [hc0..hc0+32) ----
        {
            float2 z[4];
#pragma unroll
            for (int gt = 0; gt < 4; gt++) {
                float2 v = zx[gt];
#pragma unroll
                for (int kp = 0; kp < 4; kp++)
                    v = add2(v, __ldcg((const float2*)(
                        zp + ((size_t)(g * 4 + kp) * 128 + gb) * 128 + gt * 32 + rc)));
                z[gt] = v;
            }
            float2 hn;
            {
                const float ig = sigf(z[0].x);
                const float jg = tanhf(z[1].x);
                const float fg = sigf(z[2].x + 1.0f);   // FORGET_BIAS
                const float og = sigf(z[3].x);
                creg.x = creg.x * fg + ig * jg;
                hn.x = tanhf(creg.x) * og;
            }
            {
                const float ig = sigf(z[0].y);
                const float jg = tanhf(z[1].y);
                const float fg = sigf(z[2].y + 1.0f);
                const float og = sigf(z[3].y);
                creg.y = creg.y * fg + ig * jg;
                hn.y = tanhf(creg.y) * og;
            }
            const float2 ho = make_float2(f2tf(hn.x), f2tf(hn.y));
            *(float2*)(g_hbuf[(t + 1) % 3] + (size_t)gb * H_ + ghc) = ho;
            if (dec)
                *(float2*)(g_hs + ((size_t)st * B_ + gb) * H_ + ghc) = ho;
        }

        // ---- signal gates done (consumed by step t+1 / buffer guard t+2) ----
        __syncthreads();
        __threadfence();
        if (tid == 0) *(volatile unsigned*)&g_flagH[bid * 8] = (unsigned)(t + 1);
    }
}

// ============================================================================
// mm_tf32 (R8, passing): MODE 1 (dec XG, gather), MODE 2 (projection)
// ============================================================================
#define ASTR 20
#define BSTR 136
struct TIds {
    int lane, wid, wm, wn, gid, tig;
    int ar, ak, bk, bn;
};
__device__ __forceinline__ TIds make_ids(int tid) {
    TIds s;
    s.lane = tid & 31; s.wid = tid >> 5;
    s.wm = s.wid >> 2; s.wn = s.wid & 3;
    s.gid = s.lane >> 2; s.tig = s.lane & 3;
    s.ar = tid >> 2; s.ak = (tid & 3) * 4;
    s.bk = tid >> 5; s.bn = (tid & 31) * 4;
    return s;
}
__device__ __forceinline__ void compute_bk16(
    const float* a_s, const float* b_s, const TIds& s, float acc[2][4][4])
{
#pragma unroll
    for (int ks = 0; ks < 16; ks += 8) {
        float af[2][4], bf[4][2];
#pragma unroll
        for (int mf = 0; mf < 2; mf++) {
            const int m = s.wm * 32 + mf * 16 + s.gid;
            af[mf][0] = a_s[(m)     * ASTR + ks + s.tig];
            af[mf][1] = a_s[(m + 8) * ASTR + ks + s.tig];
            af[mf][2] = a_s[(m)     * ASTR + ks + s.tig + 4];
            af[mf][3] = a_s[(m + 8) * ASTR + ks + s.tig + 4];
        }
#pragma unroll
        for (int nf = 0; nf < 4; nf++) {
            const int n = s.wn * 32 + nf * 8 + s.gid;
            bf[nf][0] = b_s[(ks + s.tig)     * BSTR + n];
            bf[nf][1] = b_s[(ks + s.tig + 4) * BSTR + n];
        }
#pragma unroll
        for (int mf = 0; mf < 2; mf++)
#pragma unroll
            for (int nf = 0; nf < 4; nf++) mma8(acc[mf][nf], af[mf], bf[nf]);
    }
}

template <int MODE>
__global__ void __launch_bounds__(512)
mm_tf32(const float* __restrict__ A, const float* __restrict__ Bm,
        const float* __restrict__ bias, float* __restrict__ Cout,
        const int* __restrict__ caption, int Kv, int ldb)
{
    __shared__ __align__(16) float a_s[2][128 * ASTR];
    __shared__ __align__(16) float b_s[2][16 * BSTR];

    const int tid = threadIdx.x;
    const TIds s = make_ids(tid);
    const int n0 = blockIdx.x * 128;
    const int mtile = blockIdx.y;

    const int m = mtile * 128 + s.ar;
    size_t aoff;
    if constexpr (MODE == 1)
        aoff = (size_t)caption[(m & 127) * L_ + (m >> 7)] * WV_;
    else
        aoff = (size_t)m * H_;
    const float* arow = ((MODE == 2) ? (const float*)g_hs : A) + aoff;

    float acc[2][4][4] = {};
    const int NK = (Kv + 15) / 16;

    auto stage = [&](int it, int buf) {
        const int kb = it * 16;
        {
            const int gk = kb + s.ak;
            float4 v = make_float4(0.f, 0.f, 0.f, 0.f);
            if (MODE != 1 || gk < Kv) v = *(const float4*)(arow + gk);
            *(float4*)&a_s[buf][s.ar * ASTR + s.ak] = tf4(v);
        }
        {
            const int gk = kb + s.bk;
            const int gn = n0 + s.bn;
            float4 v = make_float4(0.f, 0.f, 0.f, 0.f);
            const bool kok = (MODE == 1) ? (gk < Kv) : true;
            const bool nok = (MODE == 2) ? (gn < WV_) : true;
            if (kok && nok) v = *(const float4*)(Bm + (size_t)gk * ldb + gn);
            *(float4*)&b_s[buf][s.bk * BSTR + s.bn] = tf4(v);
        }
    };

    stage(0, 0);
    __syncthreads();
    int buf = 0;
    for (int it = 0; it < NK; ++it) {
        if (it + 1 < NK) stage(it + 1, buf ^ 1);
        compute_bk16(a_s[buf], b_s[buf], s, acc);
        __syncthreads();
        buf ^= 1;
    }

#pragma unroll
    for (int mf = 0; mf < 2; mf++)
#pragma unroll
        for (int nf = 0; nf < 4; nf++) {
            const int col = n0 + s.wn * 32 + nf * 8 + 2 * s.tig;
            const int mrow = mtile * 128 + s.wm * 32 + mf * 16 + s.gid;
#pragma unroll
            for (int r = 0; r < 2; r++) {
                const int row = mrow + r * 8;
                const float v0 = acc[mf][nf][2 * r];
                const float v1 = acc[mf][nf][2 * r + 1];
                if constexpr (MODE == 2) {
                    if (col < WV_) {
                        const size_t co = (size_t)((row & 127) * L_ + (row >> 7)) * WV_;
                        Cout[co + col]     = v0 + bias[col];
                        Cout[co + col + 1] = v1 + bias[col + 1];
                    }
                } else {
                    float* dst = g_xg_dec + (size_t)row * G4H + col;
                    *(float2*)dst = make_float2(v0 + bias[col], v1 + bias[col + 1]);
                }
            }
        }
}

// ---- prep kernels (R8, passing) ----
__global__ void __launch_bounds__(512)
conv_wh(const float* __restrict__ encK, const float* __restrict__ decK)
{
    const size_t i4 = ((size_t)blockIdx.x * 512 + threadIdx.x) * 4;
    if (i4 < (size_t)H_ * G4H) {
        *(float4*)&g_whE[i4] = tf4(*(const float4*)(encK + (size_t)F_  * G4H + i4));
        *(float4*)&g_whD[i4] = tf4(*(const float4*)(decK + (size_t)WV_ * G4H + i4));
    }
}

__global__ void __launch_bounds__(512)
conv_wx(const float* __restrict__ encK)
{
    const size_t i4 = ((size_t)blockIdx.x * 512 + threadIdx.x) * 4;
    if (i4 < (size_t)F_ * G4H)
        *(float4*)&g_wx[i4] = tf4(*(const float4*)(encK + i4));
}

__global__ void __launch_bounds__(512)
prep_frames(const float* __restrict__ frames)
{
    const size_t i4 = ((size_t)blockIdx.x * 512 + threadIdx.x) * 4;
    if (i4 < (size_t)4096 * F_) {
        const int m = (int)(i4 / F_), k = (int)(i4 % F_);
        const int b = m & 127, t = m >> 7;
        const float4 v = *(const float4*)(frames + ((size_t)b * T_ + t) * F_ + k);
        *(float4*)&g_frames_tf[i4] = tf4(v);
    }
}

__global__ void init_k()
{
    const int i = blockIdx.x * 256 + threadIdx.x;
    if (i < B_ * H_) g_hbuf[0][i] = 0.f;
    if (i < NBLK * 8) { g_flagZ[i] = 0u; g_flagH[i] = 0u; }
}

// ----------------------------------------------------------------------------
extern "C" void kernel_launch(void* const* d_in, const int* in_sizes, int n_in,
                              void* d_out, int out_size)
{
    const float* frames  = (const float*)d_in[0];
    const int*   caption = (const int*)  d_in[1];
    const float* emb     = (const float*)d_in[2];
    const float* encK    = (const float*)d_in[3];
    const float* encB    = (const float*)d_in[4];
    const float* decK    = (const float*)d_in[5];
    const float* decB    = (const float*)d_in[6];
    const float* projW   = (const float*)d_in[7];
    const float* projB   = (const float*)d_in[8];
    float*       out     = (float*)d_out;

    cudaFuncSetAttribute(mm0_big, cudaFuncAttributeMaxDynamicSharedMemorySize, SMEM_BIG);
    cudaFuncSetAttribute(lstm_persist, cudaFuncAttributeMaxDynamicSharedMemorySize, SMEM_PST);

    init_k<<<512, 256>>>();
    conv_wh<<<2048, 512>>>(encK, decK);
    conv_wx<<<4096, 512>>>(encK);
    prep_frames<<<4096, 512>>>(frames);

    // encoder input gates: [4096,2048] x [2048,4096] + enc_bias
    mm0_big<<<dim3(16, 32), 512, SMEM_BIG>>>(encB);

    // decoder input gates: gather(emb) [2560,300] x [300,4096] + dec_bias
    mm_tf32<1><<<dim3(32, 20), 512>>>(emb, decK, decB, nullptr, caption, WV_, G4H);

    // full recurrence (32 enc + 20 dec): BK=32 GEMM + relaxed producer sync
    lstm_persist<<<NBLK, 512, SMEM_PST>>>();

    // projection: [2560,1024] x [1024,300] + proj_b -> out[b][l][wv]
    mm_tf32<2><<<dim3(3, 20), 512>>>(nullptr, projW, projB, out, nullptr, H_, WV_);
}